// round 16
// baseline (speedup 1.0000x reference)
#include <cuda_runtime.h>
#include <math.h>
#include <stdint.h>

#define BB 8
#define NN 64
#define HH 512
#define NHEADS 8
#define NLAYERS 4
#define FFD 2048
#define NE 32768            // B*N*N edges
#define ROWS 512            // B*N
#define INV_SCALE 0.04419417382415922f  // 1/sqrt(512)

static __device__ __forceinline__ float warpReduceSum(float v) {
    #pragma unroll
    for (int o = 16; o > 0; o >>= 1) v += __shfl_xor_sync(0xffffffffu, v, o);
    return v;
}

static __device__ __forceinline__ uint32_t f2tf32(float f) {
    uint32_t u;
    asm("cvt.rna.tf32.f32 %0, %1;" : "=r"(u) : "f"(f));
    return u;
}

static __device__ __forceinline__ void mma_tf32(float* c, const uint32_t* a, const uint32_t* b) {
    asm volatile("mma.sync.aligned.m16n8k8.row.col.f32.tf32.tf32.f32 "
                 "{%0,%1,%2,%3}, {%4,%5,%6,%7}, {%8,%9}, {%0,%1,%2,%3};"
                 : "+f"(c[0]), "+f"(c[1]), "+f"(c[2]), "+f"(c[3])
                 : "r"(a[0]), "r"(a[1]), "r"(a[2]), "r"(a[3]), "r"(b[0]), "r"(b[1]));
}

static __device__ __forceinline__ void cpasync16(void* smem_dst, const void* gmem_src) {
    uint32_t d = (uint32_t)__cvta_generic_to_shared(smem_dst);
    asm volatile("cp.async.ca.shared.global [%0], [%1], 16;\n" :: "r"(d), "l"(gmem_src));
}

// ---------------- scratch (device globals; zero-init, no allocation) ----------------
__device__ __align__(128) float g_x[ROWS * HH];
__device__ __align__(128) float g_xn[ROWS * HH];
__device__ __align__(128) float g_q[ROWS * HH];
__device__ __align__(128) float g_k[ROWS * HH];
__device__ __align__(128) float g_v[ROWS * HH];
__device__ __align__(128) float g_o[ROWS * HH];
__device__ __align__(128) float g_resid[ROWS * HH];
__device__ __align__(128) float g_h1[ROWS * HH];
__device__ __align__(128) float g_ff[ROWS * FFD];
__device__ __align__(128) float g_part[4 * ROWS * HH];   // split-K partials
__device__ __align__(128) float g_Va[3 * ROWS * HH];
__device__ __align__(128) float g_Vb[3 * ROWS * HH];
__device__ __align__(128) float g_PsiA[64 * HH];   // rows 8..63 stay 0
__device__ __align__(128) float g_PsiB[64 * HH];
__device__ float g_p0[NE];
__device__ float g_pi[3 * NE];
__device__ float g_pj[3 * NE];
__device__ float g_PV[3 * BB * NN * NN];           // [t][b][n][m]
__device__ float g_PX[BB * NN * NN];               // [b][n][m]
__device__ float g_PsiGram[BB * NN * NN];          // [b][n][m]
__device__ float g_G[9 * BB * NN * NN];            // [s*3+t][b][n][m]
__device__ float g_VX[3 * BB * NN * NN];           // [t][b][n][m]

// ---------------- fused init: embed+LN per row; psi copy; p0 init ----------------
__global__ void init_ln_kernel(const int* __restrict__ ib, const float* __restrict__ aemb,
                               const float* __restrict__ bemb,
                               float* __restrict__ x, float* __restrict__ xn,
                               float* __restrict__ psi, float* __restrict__ p0) {
    __shared__ float sh[8];
    int row = blockIdx.x;          // 512
    int t = threadIdx.x;           // 256
    if (row < 8) {
        psi[row * HH + t] = bemb[row * HH + t];
        psi[row * HH + t + 256] = bemb[row * HH + t + 256];
    }
    if (t < 64) p0[row * 64 + t] = 1.0f;

    const float* e = aemb + (size_t)ib[row] * HH;
    float v0 = e[t], v1 = e[t + 256];
    x[(size_t)row * HH + t] = v0;
    x[(size_t)row * HH + t + 256] = v1;

    int lane = t & 31, w = t >> 5;
    float s = warpReduceSum(v0 + v1);
    if (lane == 0) sh[w] = s;
    __syncthreads();
    if (w == 0) {
        float y = (lane < 8) ? sh[lane] : 0.f;
        y = warpReduceSum(y);
        if (lane == 0) sh[0] = y;
    }
    __syncthreads();
    float mean = sh[0] * (1.f / HH);
    __syncthreads();
    float d0 = v0 - mean, d1 = v1 - mean;
    float vs = warpReduceSum(d0 * d0 + d1 * d1);
    if (lane == 0) sh[w] = vs;
    __syncthreads();
    if (w == 0) {
        float y = (lane < 8) ? sh[lane] : 0.f;
        y = warpReduceSum(y);
        if (lane == 0) sh[0] = y;
    }
    __syncthreads();
    float rinv = rsqrtf(sh[0] * (1.f / HH) + 1e-5f);
    xn[(size_t)row * HH + t] = d0 * rinv;
    xn[(size_t)row * HH + t + 256] = d1 * rinv;
}

// ---------------- combine split-K partials + residual, then LayerNorm ----------------
__global__ void ln_combine_kernel(const float* __restrict__ P0, const float* __restrict__ P1,
                                  const float* __restrict__ P2, const float* __restrict__ P3,
                                  const float* __restrict__ D,
                                  float* __restrict__ X, float* __restrict__ XN) {
    __shared__ float sh[8];
    int row = blockIdx.x;
    int t = threadIdx.x; // 256
    size_t base = (size_t)row * HH;
    float v0 = D[base + t] + P0[base + t] + P1[base + t] + P2[base + t] + P3[base + t];
    float v1 = D[base + t + 256] + P0[base + t + 256] + P1[base + t + 256]
             + P2[base + t + 256] + P3[base + t + 256];
    X[base + t] = v0;
    X[base + t + 256] = v1;

    int lane = t & 31, w = t >> 5;
    float s = warpReduceSum(v0 + v1);
    if (lane == 0) sh[w] = s;
    __syncthreads();
    if (w == 0) {
        float x = (lane < 8) ? sh[lane] : 0.f;
        x = warpReduceSum(x);
        if (lane == 0) sh[0] = x;
    }
    __syncthreads();
    float mean = sh[0] * (1.f / HH);
    __syncthreads();
    float d0 = v0 - mean, d1 = v1 - mean;
    float vs = warpReduceSum(d0 * d0 + d1 * d1);
    if (lane == 0) sh[w] = vs;
    __syncthreads();
    if (w == 0) {
        float x = (lane < 8) ? sh[lane] : 0.f;
        x = warpReduceSum(x);
        if (lane == 0) sh[0] = x;
    }
    __syncthreads();
    float rinv = rsqrtf(sh[0] * (1.f / HH) + 1e-5f);
    XN[base + t] = d0 * rinv;
    XN[base + t + 256] = d1 * rinv;
}

// ---------------- batched-job TF32 TC GEMM, cp.async double-buffered (CK=32) ----------
// mode 0: C = AB ; 1: C = AB + D ; 2: C = relu(AB)
struct GJob {
    const float* A; const float* B; const float* D; float* C;
    int M, N, K, mode, blkStart, kStart, kCount;
};
struct GParams { GJob jobs[8]; int nJobs; };

__global__ __launch_bounds__(256) void gemm_tc_kernel(GParams P) {
    int bx = blockIdx.x;
    int jb = 0;
    #pragma unroll
    for (int t = 1; t < 8; t++)
        if (t < P.nJobs && bx >= P.jobs[t].blkStart) jb = t;
    GJob job = P.jobs[jb];
    int tile = bx - job.blkStart;
    int tilesN = job.N >> 6;
    int tm = tile / tilesN, tn = tile - tm * tilesN;
    int N = job.N, K = job.K;
    int rowBase = tm * 64, colBase = tn * 64;

    __shared__ float As[2][64][36];   // stride 36 (≡4 mod 32)
    __shared__ float Bs[2][32][72];   // stride 72 (≡8 mod 32)

    int tid = threadIdx.x;
    int lane = tid & 31, wid = tid >> 5;
    int wm = wid >> 2;
    int wn = wid & 3;
    int g = lane >> 2, t4 = lane & 3;

    float acc[2][2][4];
    #pragma unroll
    for (int mf = 0; mf < 2; mf++)
        #pragma unroll
        for (int nf = 0; nf < 2; nf++)
            #pragma unroll
            for (int r = 0; r < 4; r++) acc[mf][nf][r] = 0.f;

    int arow = tid >> 3, ac4 = tid & 7;
    int brow = tid >> 4, bc4 = tid & 15;

    const float* Abase = job.A + (size_t)rowBase * K + job.kStart;
    const float* Bbase = job.B + (size_t)job.kStart * N + colBase;

    int nk = job.kCount >> 5;
    {
        cpasync16(&As[0][arow][ac4 * 4], Abase + (size_t)arow * K + ac4 * 4);
        cpasync16(&As[0][arow + 32][ac4 * 4], Abase + (size_t)(arow + 32) * K + ac4 * 4);
        cpasync16(&Bs[0][brow][bc4 * 4], Bbase + (size_t)brow * N + bc4 * 4);
        cpasync16(&Bs[0][brow + 16][bc4 * 4], Bbase + (size_t)(brow + 16) * N + bc4 * 4);
        asm volatile("cp.async.commit_group;\n");
    }

    for (int i = 0; i < nk; i++) {
        if (i + 1 < nk) {
            int k0 = (i + 1) << 5;
            int st = (i + 1) & 1;
            cpasync16(&As[st][arow][ac4 * 4], Abase + (size_t)arow * K + k0 + ac4 * 4);
            cpasync16(&As[st][arow + 32][ac4 * 4], Abase + (size_t)(arow + 32) * K + k0 + ac4 * 4);
            cpasync16(&Bs[st][brow][bc4 * 4], Bbase + (size_t)(k0 + brow) * N + bc4 * 4);
            cpasync16(&Bs[st][brow + 16][bc4 * 4], Bbase + (size_t)(k0 + brow + 16) * N + bc4 * 4);
            asm volatile("cp.async.commit_group;\n");
            asm volatile("cp.async.wait_group 1;\n");
        } else {
            asm volatile("cp.async.wait_group 0;\n");
        }
        __syncthreads();
        int st = i & 1;
        #pragma unroll
        for (int ks = 0; ks < 4; ks++) {
            uint32_t a[2][4], b[2][2];
            #pragma unroll
            for (int mf = 0; mf < 2; mf++) {
                int r0 = wm * 32 + mf * 16;
                a[mf][0] = f2tf32(As[st][r0 + g][ks * 8 + t4]);
                a[mf][1] = f2tf32(As[st][r0 + 8 + g][ks * 8 + t4]);
                a[mf][2] = f2tf32(As[st][r0 + g][ks * 8 + t4 + 4]);
                a[mf][3] = f2tf32(As[st][r0 + 8 + g][ks * 8 + t4 + 4]);
            }
            #pragma unroll
            for (int nf = 0; nf < 2; nf++) {
                int c0 = wn * 16 + nf * 8;
                b[nf][0] = f2tf32(Bs[st][ks * 8 + t4][c0 + g]);
                b[nf][1] = f2tf32(Bs[st][ks * 8 + t4 + 4][c0 + g]);
            }
            #pragma unroll
            for (int mf = 0; mf < 2; mf++)
                #pragma unroll
                for (int nf = 0; nf < 2; nf++)
                    mma_tf32(acc[mf][nf], a[mf], b[nf]);
        }
        __syncthreads();
    }

    #pragma unroll
    for (int mf = 0; mf < 2; mf++) {
        #pragma unroll
        for (int nf = 0; nf < 2; nf++) {
            int colb = colBase + wn * 16 + nf * 8 + t4 * 2;
            #pragma unroll
            for (int half = 0; half < 2; half++) {
                int row = rowBase + wm * 32 + mf * 16 + g + half * 8;
                float vx = acc[mf][nf][half * 2 + 0];
                float vy = acc[mf][nf][half * 2 + 1];
                size_t off = (size_t)row * N + colb;
                if (job.mode == 1) {
                    vx += job.D[off];
                    vy += job.D[off + 1];
                } else if (job.mode == 2) {
                    vx = fmaxf(vx, 0.f);
                    vy = fmaxf(vy, 0.f);
                }
                *(float2*)&job.C[off] = make_float2(vx, vy);
            }
        }
    }
}

// ---------------- fused MMA attention: 2 CTAs per (b,h), 512 threads, 16 warps -------
// warp tile 16x8: wm = wid>>3 (0..1), wn = wid&7 (0..7)
__global__ __launch_bounds__(512) void attn_fused_kernel(
    const float* __restrict__ q, const float* __restrict__ k, const float* __restrict__ v,
    const float* __restrict__ s0, const float* __restrict__ s1, const float* __restrict__ s2,
    const float* __restrict__ Psi, const int* __restrict__ adj,
    const float* __restrict__ p0, const float* __restrict__ pi, const float* __restrict__ pj,
    int T, float* __restrict__ o) {
    __shared__ float Qs[32][68];
    __shared__ float Ss[64][72];
    __shared__ float qps[32][8];
    __shared__ float diag[32];

    int bx = blockIdx.x;
    int bh = bx >> 1, hb = bx & 1;
    int b = bh >> 3, h = bh & 7;
    int i0 = hb * 32;
    int tid = threadIdx.x;           // 0..511
    int lane = tid & 31, wid = tid >> 5;   // 16 warps
    int wm = wid >> 3, wn = wid & 7;       // 16-row x 8-col warp tile
    int g = lane >> 2, t4 = lane & 3;
    int rb = b * 64;
    const float* srcs[3] = {s0, s1, s2};

    // load Q rows [i0,i0+32): 512 float4, 1 per thread
    {
        int i = tid >> 4, dg = tid & 15;
        float4 f = *(const float4*)&q[(size_t)(rb + i0 + i) * HH + h * 64 + dg * 4];
        *(float4*)&Qs[i][dg * 4] = f;
    }
    // load K^T into Ss [d][j]: 1024 float4, 2 per thread
    #pragma unroll
    for (int r = 0; r < 2; r++) {
        int idx = tid + r * 512;
        int j = idx & 63, dg = idx >> 6;
        float4 f = *(const float4*)&k[(size_t)(rb + j) * HH + h * 64 + dg * 4];
        Ss[dg * 4 + 0][j] = f.x;
        Ss[dg * 4 + 1][j] = f.y;
        Ss[dg * 4 + 2][j] = f.z;
        Ss[dg * 4 + 3][j] = f.w;
    }
    __syncthreads();

    // prefetch first pipelined operand
    float4 pf[2];
    {
        const float* nxt = (T > 0) ? srcs[0] : v;
        #pragma unroll
        for (int r = 0; r < 2; r++) {
            int idx = tid + r * 512;
            int j = (T > 0) ? (idx & 63) : (idx >> 4);
            int dg = (T > 0) ? (idx >> 6) : (idx & 15);
            pf[r] = *(const float4*)&nxt[(size_t)(rb + j) * HH + h * 64 + dg * 4];
        }
    }

    // qps[i][e] (256 entries; first 256 threads)
    if (tid < 256) {
        int i = tid >> 3, e = tid & 7;
        float s = 0.f;
        #pragma unroll 8
        for (int d = 0; d < 64; d++) s += Qs[i][d] * Psi[e * HH + h * 64 + d];
        qps[i][e] = s;
    }

    // warp MMA pass: 16x8 tile, acc2[4]
    auto mma_pass = [&](const float* A, int lda, const float* Bsm, int ldb, float acc2[4]) {
        #pragma unroll
        for (int ks = 0; ks < 8; ks++) {
            uint32_t a[4], bf[2];
            int r0 = wm * 16;
            a[0] = f2tf32(A[(r0 + g) * lda + ks * 8 + t4]);
            a[1] = f2tf32(A[(r0 + 8 + g) * lda + ks * 8 + t4]);
            a[2] = f2tf32(A[(r0 + g) * lda + ks * 8 + t4 + 4]);
            a[3] = f2tf32(A[(r0 + 8 + g) * lda + ks * 8 + t4 + 4]);
            int c0 = wn * 8;
            bf[0] = f2tf32(Bsm[(ks * 8 + t4) * ldb + c0 + g]);
            bf[1] = f2tf32(Bsm[(ks * 8 + t4 + 4) * ldb + c0 + g]);
            mma_tf32(acc2, a, bf);
        }
    };

    float acc[4];
    #pragma unroll
    for (int r = 0; r < 4; r++) acc[r] = 0.f;
    mma_pass(&Qs[0][0], 68, &Ss[0][0], 72, acc);

    for (int t = 0; t < T; t++) {
        __syncthreads();
        // STS current source (transposed)
        #pragma unroll
        for (int r = 0; r < 2; r++) {
            int idx = tid + r * 512;
            int j = idx & 63, dg = idx >> 6;
            Ss[dg * 4 + 0][j] = pf[r].x;
            Ss[dg * 4 + 1][j] = pf[r].y;
            Ss[dg * 4 + 2][j] = pf[r].z;
            Ss[dg * 4 + 3][j] = pf[r].w;
        }
        {
            bool more = (t + 1 < T);
            const float* nxt = more ? srcs[t + 1] : v;
            #pragma unroll
            for (int r = 0; r < 2; r++) {
                int idx = tid + r * 512;
                int j = more ? (idx & 63) : (idx >> 4);
                int dg = more ? (idx >> 6) : (idx & 15);
                pf[r] = *(const float4*)&nxt[(size_t)(rb + j) * HH + h * 64 + dg * 4];
            }
        }
        __syncthreads();

        // prefetch pi/pj (4 cells per lane: ch x cc)
        float pir[4], pjr[4];
        {
            int m = 0;
            #pragma unroll
            for (int ch = 0; ch < 2; ch++)
                #pragma unroll
                for (int cc = 0; cc < 2; cc++) {
                    int row = i0 + wm * 16 + g + ch * 8;
                    int col = wn * 8 + t4 * 2 + cc;
                    int bij = (rb + row) * 64 + col;
                    pir[m] = pi[t * NE + bij];
                    pjr[m] = pj[t * NE + bij];
                    m++;
                }
        }

        float mt[4];
        #pragma unroll
        for (int r = 0; r < 4; r++) mt[r] = 0.f;
        mma_pass(&Qs[0][0], 68, &Ss[0][0], 72, mt);

        // diagonal of M_t (global row == global col)
        #pragma unroll
        for (int ch = 0; ch < 2; ch++)
            #pragma unroll
            for (int cc = 0; cc < 2; cc++) {
                int rl = wm * 16 + g + ch * 8;
                int col = wn * 8 + t4 * 2 + cc;
                if (i0 + rl == col) diag[rl] = mt[ch * 2 + cc];
            }
        __syncthreads();

        {
            int m = 0;
            #pragma unroll
            for (int ch = 0; ch < 2; ch++)
                #pragma unroll
                for (int cc = 0; cc < 2; cc++) {
                    int rl = wm * 16 + g + ch * 8;
                    acc[ch * 2 + cc] += pir[m] * diag[rl] + pjr[m] * mt[ch * 2 + cc];
                    m++;
                }
        }
    }

    __syncthreads();
    // STS V (direct [j][d])
    #pragma unroll
    for (int r = 0; r < 2; r++) {
        int idx = tid + r * 512;
        int j = idx >> 4, dg = idx & 15;
        *(float4*)&Ss[j][dg * 4] = pf[r];
    }
    float* sl = &Qs[0][0];
    #pragma unroll
    for (int ch = 0; ch < 2; ch++)
        #pragma unroll
        for (int cc = 0; cc < 2; cc++) {
            int rl = wm * 16 + g + ch * 8;
            int col = wn * 8 + t4 * 2 + cc;
            int bij = (rb + i0 + rl) * 64 + col;
            int e = adj[bij];
            float val;
            if (e > 0)
                val = (acc[ch * 2 + cc] + p0[bij] * qps[rl][e]) * INV_SCALE;
            else
                val = -INFINITY;
            sl[rl * 68 + col] = val;
        }
    __syncthreads();

    // softmax: warp w handles rows w*2..w*2+1
    #pragma unroll
    for (int ri = 0; ri < 2; ri++) {
        int r = wid * 2 + ri;
        float x0 = sl[r * 68 + lane], x1 = sl[r * 68 + lane + 32];
        float m = fmaxf(x0, x1);
        #pragma unroll
        for (int off2 = 16; off2 > 0; off2 >>= 1) m = fmaxf(m, __shfl_xor_sync(0xffffffffu, m, off2));
        float e0 = expf(x0 - m), e1 = expf(x1 - m);
        float se = warpReduceSum(e0 + e1);
        float inv = 1.f / se;
        sl[r * 68 + lane] = e0 * inv;
        sl[r * 68 + lane + 32] = e1 * inv;
    }
    __syncthreads();

    // O = attn @ V
    float oacc[4];
    #pragma unroll
    for (int r = 0; r < 4; r++) oacc[r] = 0.f;
    mma_pass(sl, 68, &Ss[0][0], 72, oacc);

    {
        int colb = wn * 8 + t4 * 2;
        #pragma unroll
        for (int ch = 0; ch < 2; ch++) {
            int rl = wm * 16 + g + ch * 8;
            size_t off = (size_t)(rb + i0 + rl) * HH + h * 64 + colb;
            *(float2*)&o[off] = make_float2(oacc[ch * 2 + 0], oacc[ch * 2 + 1]);
        }
    }
}

// ---------------- batched [64,64] Gram over 512, cp.async pipelined -----------------
struct DJob { const float* A; const float* B; float* C; int strA, strB, strC; };
struct DParams { DJob jobs[16]; int n; };
__global__ __launch_bounds__(256) void gram_kernel(DParams P) {
    DJob job = P.jobs[blockIdx.x];
    int b = blockIdx.y;
    __shared__ float As[2][64][36];
    __shared__ float Bs[2][64][36];
    int tid = threadIdx.x;
    int lane = tid & 31, wid = tid >> 5;
    int wm = wid >> 2, wn = wid & 3;
    int g = lane >> 2, t4 = lane & 3;

    const float* Abase = job.A + (size_t)b * job.strA * HH;
    const float* Bbase = job.B + (size_t)b * job.strB * HH;

    int lrow = tid >> 2;
    int lc = tid & 3;

    float acc[2][2][4];
    #pragma unroll
    for (int mf = 0; mf < 2; mf++)
        #pragma unroll
        for (int nf = 0; nf < 2; nf++)
            #pragma unroll
            for (int r = 0; r < 4; r++) acc[mf][nf][r] = 0.f;

    {
        #pragma unroll
        for (int r = 0; r < 2; r++) {
            int c4 = lc + 4 * r;
            cpasync16(&As[0][lrow][c4 * 4], Abase + (size_t)lrow * HH + c4 * 4);
        }
        #pragma unroll
        for (int r = 0; r < 2; r++) {
            int c4 = lc + 4 * r;
            cpasync16(&Bs[0][lrow][c4 * 4], Bbase + (size_t)lrow * HH + c4 * 4);
        }
        asm volatile("cp.async.commit_group;\n");
    }

    for (int kc = 0; kc < 16; kc++) {
        if (kc + 1 < 16) {
            int st = (kc + 1) & 1;
            int k0 = (kc + 1) * 32;
            #pragma unroll
            for (int r = 0; r < 2; r++) {
                int c4 = lc + 4 * r;
                cpasync16(&As[st][lrow][c4 * 4], Abase + (size_t)lrow * HH + k0 + c4 * 4);
            }
            #pragma unroll
            for (int r = 0; r < 2; r++) {
                int c4 = lc + 4 * r;
                cpasync16(&Bs[st][lrow][c4 * 4], Bbase + (size_t)lrow * HH + k0 + c4 * 4);
            }
            asm volatile("cp.async.commit_group;\n");
            asm volatile("cp.async.wait_group 1;\n");
        } else {
            asm volatile("cp.async.wait_group 0;\n");
        }
        __syncthreads();
        int st = kc & 1;
        #pragma unroll
        for (int ks = 0; ks < 4; ks++) {
            uint32_t a[2][4], bb[2][2];
            #pragma unroll
            for (int mf = 0; mf < 2; mf++) {
                int r0 = wm * 32 + mf * 16;
                a[mf][0] = f2tf32(As[st][r0 + g][ks * 8 + t4]);
                a[mf][1] = f2tf32(As[st][r0 + 8 + g][ks * 8 + t4]);
                a[mf][2] = f2tf32(As[st][r0 + g][ks * 8 + t4 + 4]);
                a[mf][3] = f2tf32(As[st][r0 + 8 + g][ks * 8 + t4 + 4]);
            }
            #pragma unroll
            for (int nf = 0; nf < 2; nf++) {
                int c0 = wn * 16 + nf * 8;
                bb[nf][0] = f2tf32(Bs[st][c0 + g][ks * 8 + t4]);
                bb[nf][1] = f2tf32(Bs[st][c0 + g][ks * 8 + t4 + 4]);
            }
            #pragma unroll
            for (int mf = 0; mf < 2; mf++)
                #pragma unroll
                for (int nf = 0; nf < 2; nf++)
                    mma_tf32(acc[mf][nf], a[mf], bb[nf]);
        }
        __syncthreads();
    }
    float* out = job.C + (size_t)b * job.strC * 4096;
    #pragma unroll
    for (int mf = 0; mf < 2; mf++)
        #pragma unroll
        for (int nf = 0; nf < 2; nf++) {
            int colb = wn * 16 + nf * 8 + t4 * 2;
            #pragma unroll
            for (int half = 0; half < 2; half++) {
                int row = wm * 32 + mf * 16 + g + half * 8;
                *(float2*)&out[row * 64 + colb] = make_float2(acc[mf][nf][half * 2 + 0],
                                                              acc[mf][nf][half * 2 + 1]);
            }
        }
}

// ---------------- edge coefficient update ----------------
__global__ void edge_kernel(const int* __restrict__ adj,
                            const float* __restrict__ PG,
                            const float* __restrict__ PV,
                            const float* __restrict__ PX,
                            const float* __restrict__ G,
                            const float* __restrict__ VX,
                            float* __restrict__ p0,
                            float* __restrict__ pi,
                            float* __restrict__ pj,
                            int T) {
    int bij = blockIdx.x * blockDim.x + threadIdx.x; // 32768
    int b = bij >> 12;
    int ij = bij & 4095;
    int i = ij >> 6, j = ij & 63;
    int e = adj[bij];
    size_t tb = (size_t)b * 4096;

    float P0 = p0[bij];
    float s = P0 * P0 * PG[tb + e * 64 + e];
    float a0 = P0 * PX[tb + i * 64 + e];
    float a1 = P0 * PX[tb + j * 64 + e];

    float ci[3], cj[3];
    for (int t = 0; t < T; t++) { ci[t] = pi[t * NE + bij]; cj[t] = pj[t * NE + bij]; }

    for (int t = 0; t < T; t++) {
        const float* pv = PV + (size_t)t * NE + tb;
        s += 2.f * P0 * (ci[t] * pv[i * 64 + e] + cj[t] * pv[j * 64 + e]);
        const float* vx = VX + (size_t)t * NE + tb;
        a0 += ci[t] * vx[i * 64 + i] + cj[t] * vx[j * 64 + i];
        a1 += ci[t] * vx[i * 64 + j] + cj[t] * vx[j * 64 + j];
        for (int ss2 = 0; ss2 < T; ss2++) {
            const float* g = G + (size_t)(ss2 * 3 + t) * NE + tb;
            s += ci[ss2] * ci[t] * g[i * 64 + i]
               + cj[ss2] * cj[t] * g[j * 64 + j]
               + 2.f * ci[ss2] * cj[t] * g[i * 64 + j];
        }
    }

    float u0 = s * INV_SCALE, u1 = a0 * INV_SCALE, u2 = a1 * INV_SCALE;
    float mm = fmaxf(u0, fmaxf(u1, u2));
    float q0 = expf(u0 - mm), q1 = expf(u1 - mm), q2 = expf(u2 - mm);
    float inv = 1.f / (q0 + q1 + q2);
    float w0 = q0 * inv;

    p0[bij] = w0 * P0;
    for (int t = 0; t < T; t++) {
        pi[t * NE + bij] = w0 * ci[t];
        pj[t * NE + bij] = w0 * cj[t];
    }
    pi[T * NE + bij] = q1 * inv;
    pj[T * NE + bij] = q2 * inv;
}

// ---------------- head ----------------
__global__ __launch_bounds__(512) void head_kernel(const float* __restrict__ x,
                                                   const float* __restrict__ Wout,
                                                   const float* __restrict__ Wpred,
                                                   const float* __restrict__ bpred,
                                                   float* __restrict__ out) {
    int b = blockIdx.x;
    int t = threadIdx.x; // 512
    __shared__ float xb[HH];
    __shared__ float cvec[HH];
    __shared__ float r0[16], r1[16];
    xb[t] = x[(size_t)(b * NN) * HH + t];
    __syncthreads();
    float s = 0.f;
    #pragma unroll 8
    for (int h2 = 0; h2 < HH; h2++) s += xb[h2] * Wout[(size_t)h2 * HH + t];
    cvec[t] = tanhf(s);
    __syncthreads();
    float pr0 = cvec[t] * Wpred[t * 2 + 0];
    float pr1 = cvec[t] * Wpred[t * 2 + 1];
    pr0 = warpReduceSum(pr0);
    pr1 = warpReduceSum(pr1);
    int lane = t & 31, w = t >> 5;
    if (lane == 0) { r0[w] = pr0; r1[w] = pr1; }
    __syncthreads();
    if (t == 0) {
        float l0 = bpred[0], l1 = bpred[1];
        #pragma unroll
        for (int q2 = 0; q2 < 16; q2++) { l0 += r0[q2]; l1 += r1[q2]; }
        float m = fmaxf(l0, l1);
        float e0 = expf(l0 - m), e1 = expf(l1 - m);
        float inv = 1.f / (e0 + e1);
        out[b * 2 + 0] = e0 * inv;
        out[b * 2 + 1] = e1 * inv;
    }
}

// ---------------- orchestration ----------------
extern "C" void kernel_launch(void* const* d_in, const int* in_sizes, int n_in,
                              void* d_out, int out_size) {
    const int* input_batch = (const int*)d_in[0];
    const int* adj = (const int*)d_in[1];
    const float* atom_emb = (const float*)d_in[2];
    const float* bond_emb = (const float*)d_in[3];
    const float* Wq = (const float*)d_in[4];
    const float* Wk = (const float*)d_in[5];
    const float* Wv = (const float*)d_in[6];
    const float* Wew = (const float*)d_in[7];
    const float* Wstack = (const float*)d_in[8];
    const float* Wf1 = (const float*)d_in[9];
    const float* Wf2 = (const float*)d_in[10];
    const float* Wout = (const float*)d_in[11];
    const float* Wpred = (const float*)d_in[12];
    const float* bpred = (const float*)d_in[13];
    float* out = (float*)d_out;

    static cudaStream_t sA = nullptr;
    static cudaEvent_t evFork = nullptr, evMid = nullptr, evA = nullptr;
    static int initDone = 0;
    if (!initDone) {
        cudaStreamCreateWithFlags(&sA, cudaStreamNonBlocking);
        cudaEventCreateWithFlags(&evFork, cudaEventDisableTiming);
        cudaEventCreateWithFlags(&evMid, cudaEventDisableTiming);
        cudaEventCreateWithFlags(&evA, cudaEventDisableTiming);
        initDone = 1;
    }

    float *x, *xn, *q, *k, *v, *o, *resid, *h1, *ff, *part, *Va, *Vb, *PsiA, *PsiB;
    float *p0, *pi, *pj, *PV, *PX, *PsiGram, *G, *VX;
    cudaGetSymbolAddress((void**)&x, g_x);
    cudaGetSymbolAddress((void**)&xn, g_xn);
    cudaGetSymbolAddress((void**)&q, g_q);
    cudaGetSymbolAddress((void**)&k, g_k);
    cudaGetSymbolAddress((void**)&v, g_v);
    cudaGetSymbolAddress((void**)&o, g_o);
    cudaGetSymbolAddress((void**)&resid, g_resid);
    cudaGetSymbolAddress((void**)&h1, g_h1);
    cudaGetSymbolAddress((void**)&ff, g_ff);
    cudaGetSymbolAddress((void**)&part, g_part);
    cudaGetSymbolAddress((void**)&Va, g_Va);
    cudaGetSymbolAddress((void**)&Vb, g_Vb);
    cudaGetSymbolAddress((void**)&PsiA, g_PsiA);
    cudaGetSymbolAddress((void**)&PsiB, g_PsiB);
    cudaGetSymbolAddress((void**)&p0, g_p0);
    cudaGetSymbolAddress((void**)&pi, g_pi);
    cudaGetSymbolAddress((void**)&pj, g_pj);
    cudaGetSymbolAddress((void**)&PV, g_PV);
    cudaGetSymbolAddress((void**)&PX, g_PX);
    cudaGetSymbolAddress((void**)&PsiGram, g_PsiGram);
    cudaGetSymbolAddress((void**)&G, g_G);
    cudaGetSymbolAddress((void**)&VX, g_VX);

    float* P0b = part;
    float* P1b = part + (size_t)ROWS * HH;
    float* P2b = part + (size_t)2 * ROWS * HH;
    float* P3b = part + (size_t)3 * ROWS * HH;

    init_ln_kernel<<<ROWS, 256>>>(input_batch, atom_emb, bond_emb, x, xn, PsiA, p0);

    float* VbufA[3] = {Va, Va + ROWS * HH, Va + 2 * ROWS * HH};
    float* VbufB[3] = {Vb, Vb + ROWS * HH, Vb + 2 * ROWS * HH};
    float* prevDst[3] = {nullptr, nullptr, nullptr};
    bool pendingA = false;

    for (int l = 0; l < NLAYERS; l++) {
        const float* Wq_l = Wq + (size_t)l * HH * HH;
        const float* Wk_l = Wk + (size_t)l * HH * HH;
        const float* Wv_l = Wv + (size_t)l * HH * HH;
        const float* Wew_l = Wew + (size_t)l * HH * HH;
        const float* Wst_l = Wstack + (size_t)l * HH * HH;
        const float* Wf1_l = Wf1 + (size_t)l * HH * FFD;
        const float* Wf2_l = Wf2 + (size_t)l * FFD * HH;

        int T = l;
        float** dst = (l & 1) ? VbufA : VbufB;
        const float* src[3];
        for (int t = 0; t < T - 1; t++) src[t] = prevDst[t];
        if (T > 0) src[T - 1] = x;
        float* psiSrc = (l & 1) ? PsiB : PsiA;
        float* psiDst = (l & 1) ? PsiA : PsiB;

        // 1) fused GEMMs: q,k,v + V'_t + Psi'
        {
            GParams Pm;
            int nb = 0, blk = 0;
            auto add = [&](const float* A, const float* B2, float* C2, int M, int N2, int K2) {
                Pm.jobs[nb] = {A, B2, nullptr, C2, M, N2, K2, 0, blk, 0, K2};
                blk += (M / 64) * (N2 / 64);
                nb++;
            };
            add(xn, Wq_l, q, ROWS, HH, HH);
            add(xn, Wk_l, k, ROWS, HH, HH);
            add(xn, Wv_l, v, ROWS, HH, HH);
            for (int t = 0; t < T; t++) add(src[t], Wew_l, dst[t], ROWS, HH, HH);
            add(psiSrc, Wew_l, psiDst, 64, HH, HH);
            Pm.nJobs = nb;
            gemm_tc_kernel<<<blk, 256>>>(Pm);
        }

        // early fork: G[s,t], PV_t, PsiGram — needs only dst/psiDst
        if (l < NLAYERS - 1) {
            cudaEventRecord(evFork, 0);
            cudaStreamWaitEvent(sA, evFork, 0);
            DParams DP;
            int nj = 0;
            for (int s = 0; s < T; s++)
                for (int t = 0; t < T; t++)
                    DP.jobs[nj++] = {dst[s], dst[t], G + (size_t)(s * 3 + t) * NE, 64, 64, 1};
            for (int t = 0; t < T; t++)
                DP.jobs[nj++] = {dst[t], psiDst, PV + (size_t)t * NE, 64, 0, 1};
            DP.jobs[nj++] = {psiDst, psiDst, PsiGram, 0, 0, 1};
            DP.n = nj;
            dim3 gg(nj, BB);
            gram_kernel<<<gg, 256, 0, sA>>>(DP);
        }

        // join previous layer's edge_kernel before attention
        if (pendingA) {
            cudaStreamWaitEvent(0, evA, 0);
            pendingA = false;
        }

        // 2) fused attention: 2 CTAs per (b,h), 512 threads
        attn_fused_kernel<<<BB * NHEADS * 2, 512>>>(q, k, v,
                                                T > 0 ? dst[0] : nullptr,
                                                T > 1 ? dst[1] : nullptr,
                                                T > 2 ? dst[2] : nullptr,
                                                psiDst, adj, p0, pi, pj, T, o);

        // 3) stack GEMM, split-K x4
        {
            GParams Pm;
            for (int sK = 0; sK < 4; sK++)
                Pm.jobs[sK] = {o, Wst_l, nullptr, part + (size_t)sK * ROWS * HH,
                               ROWS, HH, HH, 0, sK * 64, sK * 128, 128};
            Pm.nJobs = 4;
            gemm_tc_kernel<<<256, 256>>>(Pm);
        }
        // 4) resid = sum(P)+xn ; h1 = LN(resid)
        ln_combine_kernel<<<ROWS, 256>>>(P0b, P1b, P2b, P3b, xn, resid, h1);

        // 5) FF1 (relu)
        {
            GParams Pm;
            Pm.jobs[0] = {h1, Wf1_l, nullptr, ff, ROWS, FFD, HH, 2, 0, 0, HH};
            Pm.nJobs = 1;
            gemm_tc_kernel<<<(ROWS / 64) * (FFD / 64), 256>>>(Pm);
        }
        // 6) FF2 split-K x4
        {
            GParams Pm;
            for (int sK = 0; sK < 4; sK++)
                Pm.jobs[sK] = {ff, Wf2_l, nullptr, part + (size_t)sK * ROWS * HH,
                               ROWS, HH, FFD, 0, sK * 64, sK * 512, 512};
            Pm.nJobs = 4;
            gemm_tc_kernel<<<256, 256>>>(Pm);
        }
        // 7) x = sum(P) + resid ; xn = LN(x)
        ln_combine_kernel<<<ROWS, 256>>>(P0b, P1b, P2b, P3b, resid, x, xn);

        // late fork: VX_t + PX (need x) as gram jobs, then edge update
        if (l < NLAYERS - 1) {
            cudaEventRecord(evMid, 0);
            cudaStreamWaitEvent(sA, evMid, 0);
            DParams DP;
            int nj = 0;
            for (int t = 0; t < T; t++)
                DP.jobs[nj++] = {dst[t], x, VX + (size_t)t * NE, 64, 64, 1};
            DP.jobs[nj++] = {x, psiDst, PX, 64, 0, 1};
            DP.n = nj;
            dim3 gg(nj, BB);
            gram_kernel<<<gg, 256, 0, sA>>>(DP);
            edge_kernel<<<NE / 256, 256, 0, sA>>>(adj, PsiGram, PV, PX, G, VX, p0, pi, pj, T);
            cudaEventRecord(evA, sA);
            pendingA = true;
        }

        prevDst[0] = dst[0]; prevDst[1] = dst[1]; prevDst[2] = dst[2];
    }

    head_kernel<<<BB, 512>>>(x, Wout, Wpred, bpred, out);
}

// round 17
// speedup vs baseline: 1.0053x; 1.0053x over previous
#include <cuda_runtime.h>
#include <math.h>
#include <stdint.h>

#define BB 8
#define NN 64
#define HH 512
#define NHEADS 8
#define NLAYERS 4
#define FFD 2048
#define NE 32768            // B*N*N edges
#define ROWS 512            // B*N
#define INV_SCALE 0.04419417382415922f  // 1/sqrt(512)

static __device__ __forceinline__ float warpReduceSum(float v) {
    #pragma unroll
    for (int o = 16; o > 0; o >>= 1) v += __shfl_xor_sync(0xffffffffu, v, o);
    return v;
}

static __device__ __forceinline__ uint32_t f2tf32(float f) {
    uint32_t u;
    asm("cvt.rna.tf32.f32 %0, %1;" : "=r"(u) : "f"(f));
    return u;
}

static __device__ __forceinline__ void mma_tf32(float* c, const uint32_t* a, const uint32_t* b) {
    asm volatile("mma.sync.aligned.m16n8k8.row.col.f32.tf32.tf32.f32 "
                 "{%0,%1,%2,%3}, {%4,%5,%6,%7}, {%8,%9}, {%0,%1,%2,%3};"
                 : "+f"(c[0]), "+f"(c[1]), "+f"(c[2]), "+f"(c[3])
                 : "r"(a[0]), "r"(a[1]), "r"(a[2]), "r"(a[3]), "r"(b[0]), "r"(b[1]));
}

static __device__ __forceinline__ void cpasync16(void* smem_dst, const void* gmem_src) {
    uint32_t d = (uint32_t)__cvta_generic_to_shared(smem_dst);
    asm volatile("cp.async.ca.shared.global [%0], [%1], 16;\n" :: "r"(d), "l"(gmem_src));
}

// ---------------- scratch (device globals; zero-init, no allocation) ----------------
__device__ __align__(128) float g_x[ROWS * HH];
__device__ __align__(128) float g_xn[ROWS * HH];
__device__ __align__(128) float g_q[ROWS * HH];
__device__ __align__(128) float g_k[ROWS * HH];
__device__ __align__(128) float g_v[ROWS * HH];
__device__ __align__(128) float g_o[ROWS * HH];
__device__ __align__(128) float g_resid[ROWS * HH];
__device__ __align__(128) float g_h1[ROWS * HH];
__device__ __align__(128) float g_ff[ROWS * FFD];
__device__ __align__(128) float g_part[4 * ROWS * HH];   // split-K partials
__device__ __align__(128) float g_Va[3 * ROWS * HH];
__device__ __align__(128) float g_Vb[3 * ROWS * HH];
__device__ __align__(128) float g_PsiA[64 * HH];   // rows 8..63 stay 0
__device__ __align__(128) float g_PsiB[64 * HH];
__device__ float g_p0[NE];
__device__ float g_pi[3 * NE];
__device__ float g_pj[3 * NE];
__device__ float g_PV[3 * BB * NN * NN];           // [t][b][n][m]
__device__ float g_PX[BB * NN * NN];               // [b][n][m]
__device__ float g_PsiGram[BB * NN * NN];          // [b][n][m]
__device__ float g_G[9 * BB * NN * NN];            // [s*3+t][b][n][m]
__device__ float g_VX[3 * BB * NN * NN];           // [t][b][n][m]

// ---------------- fused init: embed+LN per row (float4); psi copy; p0 init ----------
__global__ void init_ln_kernel(const int* __restrict__ ib, const float* __restrict__ aemb,
                               const float* __restrict__ bemb,
                               float* __restrict__ x, float* __restrict__ xn,
                               float* __restrict__ psi, float* __restrict__ p0) {
    __shared__ float sh[4];
    int row = blockIdx.x;          // 512
    int t = threadIdx.x;           // 128
    if (row < 8) {
        float4 pv = *(const float4*)&bemb[row * HH + t * 4];
        *(float4*)&psi[row * HH + t * 4] = pv;
    }
    if (t < 64) p0[row * 64 + t] = 1.0f;

    const float* e = aemb + (size_t)ib[row] * HH;
    float4 v4 = *(const float4*)&e[t * 4];
    *(float4*)&x[(size_t)row * HH + t * 4] = v4;

    int lane = t & 31, w = t >> 5;
    float s = warpReduceSum(v4.x + v4.y + v4.z + v4.w);
    if (lane == 0) sh[w] = s;
    __syncthreads();
    float mean = (sh[0] + sh[1] + sh[2] + sh[3]) * (1.f / HH);
    __syncthreads();
    float d0 = v4.x - mean, d1 = v4.y - mean, d2 = v4.z - mean, d3 = v4.w - mean;
    float vs = warpReduceSum(d0 * d0 + d1 * d1 + d2 * d2 + d3 * d3);
    if (lane == 0) sh[w] = vs;
    __syncthreads();
    float rinv = rsqrtf((sh[0] + sh[1] + sh[2] + sh[3]) * (1.f / HH) + 1e-5f);
    *(float4*)&xn[(size_t)row * HH + t * 4] =
        make_float4(d0 * rinv, d1 * rinv, d2 * rinv, d3 * rinv);
}

// ---------------- combine split-K partials + residual, then LayerNorm (float4) ------
__global__ void ln_combine_kernel(const float* __restrict__ P0, const float* __restrict__ P1,
                                  const float* __restrict__ P2, const float* __restrict__ P3,
                                  const float* __restrict__ D,
                                  float* __restrict__ X, float* __restrict__ XN) {
    __shared__ float sh[4];
    int row = blockIdx.x;
    int t = threadIdx.x; // 128
    size_t base = (size_t)row * HH + t * 4;
    float4 a = *(const float4*)&D[base];
    float4 b = *(const float4*)&P0[base];
    float4 c = *(const float4*)&P1[base];
    float4 d = *(const float4*)&P2[base];
    float4 e = *(const float4*)&P3[base];
    float v0 = a.x + b.x + c.x + d.x + e.x;
    float v1 = a.y + b.y + c.y + d.y + e.y;
    float v2 = a.z + b.z + c.z + d.z + e.z;
    float v3 = a.w + b.w + c.w + d.w + e.w;
    *(float4*)&X[base] = make_float4(v0, v1, v2, v3);

    int lane = t & 31, w = t >> 5;
    float s = warpReduceSum(v0 + v1 + v2 + v3);
    if (lane == 0) sh[w] = s;
    __syncthreads();
    float mean = (sh[0] + sh[1] + sh[2] + sh[3]) * (1.f / HH);
    __syncthreads();
    float d0 = v0 - mean, d1 = v1 - mean, d2 = v2 - mean, d3 = v3 - mean;
    float vs = warpReduceSum(d0 * d0 + d1 * d1 + d2 * d2 + d3 * d3);
    if (lane == 0) sh[w] = vs;
    __syncthreads();
    float rinv = rsqrtf((sh[0] + sh[1] + sh[2] + sh[3]) * (1.f / HH) + 1e-5f);
    *(float4*)&XN[base] = make_float4(d0 * rinv, d1 * rinv, d2 * rinv, d3 * rinv);
}

// ---------------- batched-job TF32 TC GEMM, cp.async double-buffered (CK=32) ----------
// mode 0: C = AB ; 1: C = AB + D ; 2: C = relu(AB)
struct GJob {
    const float* A; const float* B; const float* D; float* C;
    int M, N, K, mode, blkStart, kStart, kCount;
};
struct GParams { GJob jobs[8]; int nJobs; };

__global__ __launch_bounds__(256) void gemm_tc_kernel(GParams P) {
    int bx = blockIdx.x;
    int jb = 0;
    #pragma unroll
    for (int t = 1; t < 8; t++)
        if (t < P.nJobs && bx >= P.jobs[t].blkStart) jb = t;
    GJob job = P.jobs[jb];
    int tile = bx - job.blkStart;
    int tilesN = job.N >> 6;
    int tm = tile / tilesN, tn = tile - tm * tilesN;
    int N = job.N, K = job.K;
    int rowBase = tm * 64, colBase = tn * 64;

    __shared__ float As[2][64][36];   // stride 36 (≡4 mod 32)
    __shared__ float Bs[2][32][72];   // stride 72 (≡8 mod 32)

    int tid = threadIdx.x;
    int lane = tid & 31, wid = tid >> 5;
    int wm = wid >> 2;
    int wn = wid & 3;
    int g = lane >> 2, t4 = lane & 3;

    float acc[2][2][4];
    #pragma unroll
    for (int mf = 0; mf < 2; mf++)
        #pragma unroll
        for (int nf = 0; nf < 2; nf++)
            #pragma unroll
            for (int r = 0; r < 4; r++) acc[mf][nf][r] = 0.f;

    int arow = tid >> 3, ac4 = tid & 7;
    int brow = tid >> 4, bc4 = tid & 15;

    const float* Abase = job.A + (size_t)rowBase * K + job.kStart;
    const float* Bbase = job.B + (size_t)job.kStart * N + colBase;

    int nk = job.kCount >> 5;
    {
        cpasync16(&As[0][arow][ac4 * 4], Abase + (size_t)arow * K + ac4 * 4);
        cpasync16(&As[0][arow + 32][ac4 * 4], Abase + (size_t)(arow + 32) * K + ac4 * 4);
        cpasync16(&Bs[0][brow][bc4 * 4], Bbase + (size_t)brow * N + bc4 * 4);
        cpasync16(&Bs[0][brow + 16][bc4 * 4], Bbase + (size_t)(brow + 16) * N + bc4 * 4);
        asm volatile("cp.async.commit_group;\n");
    }

    for (int i = 0; i < nk; i++) {
        if (i + 1 < nk) {
            int k0 = (i + 1) << 5;
            int st = (i + 1) & 1;
            cpasync16(&As[st][arow][ac4 * 4], Abase + (size_t)arow * K + k0 + ac4 * 4);
            cpasync16(&As[st][arow + 32][ac4 * 4], Abase + (size_t)(arow + 32) * K + k0 + ac4 * 4);
            cpasync16(&Bs[st][brow][bc4 * 4], Bbase + (size_t)(k0 + brow) * N + bc4 * 4);
            cpasync16(&Bs[st][brow + 16][bc4 * 4], Bbase + (size_t)(k0 + brow + 16) * N + bc4 * 4);
            asm volatile("cp.async.commit_group;\n");
            asm volatile("cp.async.wait_group 1;\n");
        } else {
            asm volatile("cp.async.wait_group 0;\n");
        }
        __syncthreads();
        int st = i & 1;
        #pragma unroll
        for (int ks = 0; ks < 4; ks++) {
            uint32_t a[2][4], b[2][2];
            #pragma unroll
            for (int mf = 0; mf < 2; mf++) {
                int r0 = wm * 32 + mf * 16;
                a[mf][0] = f2tf32(As[st][r0 + g][ks * 8 + t4]);
                a[mf][1] = f2tf32(As[st][r0 + 8 + g][ks * 8 + t4]);
                a[mf][2] = f2tf32(As[st][r0 + g][ks * 8 + t4 + 4]);
                a[mf][3] = f2tf32(As[st][r0 + 8 + g][ks * 8 + t4 + 4]);
            }
            #pragma unroll
            for (int nf = 0; nf < 2; nf++) {
                int c0 = wn * 16 + nf * 8;
                b[nf][0] = f2tf32(Bs[st][ks * 8 + t4][c0 + g]);
                b[nf][1] = f2tf32(Bs[st][ks * 8 + t4 + 4][c0 + g]);
            }
            #pragma unroll
            for (int mf = 0; mf < 2; mf++)
                #pragma unroll
                for (int nf = 0; nf < 2; nf++)
                    mma_tf32(acc[mf][nf], a[mf], b[nf]);
        }
        __syncthreads();
    }

    #pragma unroll
    for (int mf = 0; mf < 2; mf++) {
        #pragma unroll
        for (int nf = 0; nf < 2; nf++) {
            int colb = colBase + wn * 16 + nf * 8 + t4 * 2;
            #pragma unroll
            for (int half = 0; half < 2; half++) {
                int row = rowBase + wm * 32 + mf * 16 + g + half * 8;
                float vx = acc[mf][nf][half * 2 + 0];
                float vy = acc[mf][nf][half * 2 + 1];
                size_t off = (size_t)row * N + colb;
                if (job.mode == 1) {
                    vx += job.D[off];
                    vy += job.D[off + 1];
                } else if (job.mode == 2) {
                    vx = fmaxf(vx, 0.f);
                    vy = fmaxf(vy, 0.f);
                }
                *(float2*)&job.C[off] = make_float2(vx, vy);
            }
        }
    }
}

// ---------------- fused MMA attention: 2 CTAs per (b,h), 32 rows each (R15) ----------
__global__ __launch_bounds__(256) void attn_fused_kernel(
    const float* __restrict__ q, const float* __restrict__ k, const float* __restrict__ v,
    const float* __restrict__ s0, const float* __restrict__ s1, const float* __restrict__ s2,
    const float* __restrict__ Psi, const int* __restrict__ adj,
    const float* __restrict__ p0, const float* __restrict__ pi, const float* __restrict__ pj,
    int T, float* __restrict__ o) {
    __shared__ float Qs[32][68];
    __shared__ float Ss[64][72];
    __shared__ float qps[32][8];
    __shared__ float diag[32];

    int bx = blockIdx.x;
    int bh = bx >> 1, hb = bx & 1;
    int b = bh >> 3, h = bh & 7;
    int i0 = hb * 32;
    int tid = threadIdx.x;
    int lane = tid & 31, wid = tid >> 5;
    int wm = wid >> 2, wn = wid & 3;
    int g = lane >> 2, t4 = lane & 3;
    int rb = b * 64;
    const float* srcs[3] = {s0, s1, s2};

    #pragma unroll
    for (int r = 0; r < 2; r++) {
        int idx = tid + r * 256;
        int i = idx >> 4, dg = idx & 15;
        float4 f = *(const float4*)&q[(size_t)(rb + i0 + i) * HH + h * 64 + dg * 4];
        *(float4*)&Qs[i][dg * 4] = f;
    }
    #pragma unroll
    for (int r = 0; r < 4; r++) {
        int idx = tid + r * 256;
        int j = idx & 63, dg = idx >> 6;
        float4 f = *(const float4*)&k[(size_t)(rb + j) * HH + h * 64 + dg * 4];
        Ss[dg * 4 + 0][j] = f.x;
        Ss[dg * 4 + 1][j] = f.y;
        Ss[dg * 4 + 2][j] = f.z;
        Ss[dg * 4 + 3][j] = f.w;
    }
    __syncthreads();

    float4 pf[4];
    {
        const float* nxt = (T > 0) ? srcs[0] : v;
        #pragma unroll
        for (int r = 0; r < 4; r++) {
            int idx = tid + r * 256;
            int j = (T > 0) ? (idx & 63) : (idx >> 4);
            int dg = (T > 0) ? (idx >> 6) : (idx & 15);
            pf[r] = *(const float4*)&nxt[(size_t)(rb + j) * HH + h * 64 + dg * 4];
        }
    }

    {
        int i = tid >> 3, e = tid & 7;
        float s = 0.f;
        #pragma unroll 8
        for (int d = 0; d < 64; d++) s += Qs[i][d] * Psi[e * HH + h * 64 + d];
        qps[i][e] = s;
    }

    auto mma_pass = [&](const float* A, int lda, const float* Bsm, int ldb, float acc2[2][4]) {
        #pragma unroll
        for (int ks = 0; ks < 8; ks++) {
            uint32_t a[4], bf[2][2];
            int r0 = wm * 16;
            a[0] = f2tf32(A[(r0 + g) * lda + ks * 8 + t4]);
            a[1] = f2tf32(A[(r0 + 8 + g) * lda + ks * 8 + t4]);
            a[2] = f2tf32(A[(r0 + g) * lda + ks * 8 + t4 + 4]);
            a[3] = f2tf32(A[(r0 + 8 + g) * lda + ks * 8 + t4 + 4]);
            #pragma unroll
            for (int nf = 0; nf < 2; nf++) {
                int c0 = wn * 16 + nf * 8;
                bf[nf][0] = f2tf32(Bsm[(ks * 8 + t4) * ldb + c0 + g]);
                bf[nf][1] = f2tf32(Bsm[(ks * 8 + t4 + 4) * ldb + c0 + g]);
            }
            #pragma unroll
            for (int nf = 0; nf < 2; nf++)
                mma_tf32(acc2[nf], a, bf[nf]);
        }
    };

    float acc[2][4];
    #pragma unroll
    for (int nf = 0; nf < 2; nf++)
        #pragma unroll
        for (int r = 0; r < 4; r++) acc[nf][r] = 0.f;
    mma_pass(&Qs[0][0], 68, &Ss[0][0], 72, acc);

    for (int t = 0; t < T; t++) {
        __syncthreads();
        #pragma unroll
        for (int r = 0; r < 4; r++) {
            int idx = tid + r * 256;
            int j = idx & 63, dg = idx >> 6;
            Ss[dg * 4 + 0][j] = pf[r].x;
            Ss[dg * 4 + 1][j] = pf[r].y;
            Ss[dg * 4 + 2][j] = pf[r].z;
            Ss[dg * 4 + 3][j] = pf[r].w;
        }
        {
            bool more = (t + 1 < T);
            const float* nxt = more ? srcs[t + 1] : v;
            #pragma unroll
            for (int r = 0; r < 4; r++) {
                int idx = tid + r * 256;
                int j = more ? (idx & 63) : (idx >> 4);
                int dg = more ? (idx >> 6) : (idx & 15);
                pf[r] = *(const float4*)&nxt[(size_t)(rb + j) * HH + h * 64 + dg * 4];
            }
        }
        __syncthreads();

        float pir[8], pjr[8];
        {
            int m = 0;
            #pragma unroll
            for (int nf = 0; nf < 2; nf++)
                #pragma unroll
                for (int ch = 0; ch < 2; ch++)
                    #pragma unroll
                    for (int cc = 0; cc < 2; cc++) {
                        int row = i0 + wm * 16 + g + ch * 8;
                        int col = wn * 16 + nf * 8 + t4 * 2 + cc;
                        int bij = (rb + row) * 64 + col;
                        pir[m] = pi[t * NE + bij];
                        pjr[m] = pj[t * NE + bij];
                        m++;
                    }
        }

        float mt[2][4];
        #pragma unroll
        for (int nf = 0; nf < 2; nf++)
            #pragma unroll
            for (int r = 0; r < 4; r++) mt[nf][r] = 0.f;
        mma_pass(&Qs[0][0], 68, &Ss[0][0], 72, mt);

        #pragma unroll
        for (int nf = 0; nf < 2; nf++)
            #pragma unroll
            for (int ch = 0; ch < 2; ch++)
                #pragma unroll
                for (int cc = 0; cc < 2; cc++) {
                    int rl = wm * 16 + g + ch * 8;
                    int col = wn * 16 + nf * 8 + t4 * 2 + cc;
                    if (i0 + rl == col) diag[rl] = mt[nf][ch * 2 + cc];
                }
        __syncthreads();

        {
            int m = 0;
            #pragma unroll
            for (int nf = 0; nf < 2; nf++)
                #pragma unroll
                for (int ch = 0; ch < 2; ch++)
                    #pragma unroll
                    for (int cc = 0; cc < 2; cc++) {
                        int rl = wm * 16 + g + ch * 8;
                        acc[nf][ch * 2 + cc] += pir[m] * diag[rl] + pjr[m] * mt[nf][ch * 2 + cc];
                        m++;
                    }
        }
    }

    __syncthreads();
    #pragma unroll
    for (int r = 0; r < 4; r++) {
        int idx = tid + r * 256;
        int j = idx >> 4, dg = idx & 15;
        *(float4*)&Ss[j][dg * 4] = pf[r];
    }
    float* sl = &Qs[0][0];
    #pragma unroll
    for (int nf = 0; nf < 2; nf++)
        #pragma unroll
        for (int ch = 0; ch < 2; ch++)
            #pragma unroll
            for (int cc = 0; cc < 2; cc++) {
                int rl = wm * 16 + g + ch * 8;
                int col = wn * 16 + nf * 8 + t4 * 2 + cc;
                int bij = (rb + i0 + rl) * 64 + col;
                int e = adj[bij];
                float val;
                if (e > 0)
                    val = (acc[nf][ch * 2 + cc] + p0[bij] * qps[rl][e]) * INV_SCALE;
                else
                    val = -INFINITY;
                sl[rl * 68 + col] = val;
            }
    __syncthreads();

    #pragma unroll
    for (int ri = 0; ri < 4; ri++) {
        int r = wid * 4 + ri;
        float x0 = sl[r * 68 + lane], x1 = sl[r * 68 + lane + 32];
        float m = fmaxf(x0, x1);
        #pragma unroll
        for (int off2 = 16; off2 > 0; off2 >>= 1) m = fmaxf(m, __shfl_xor_sync(0xffffffffu, m, off2));
        float e0 = expf(x0 - m), e1 = expf(x1 - m);
        float se = warpReduceSum(e0 + e1);
        float inv = 1.f / se;
        sl[r * 68 + lane] = e0 * inv;
        sl[r * 68 + lane + 32] = e1 * inv;
    }
    __syncthreads();

    float oacc[2][4];
    #pragma unroll
    for (int nf = 0; nf < 2; nf++)
        #pragma unroll
        for (int r = 0; r < 4; r++) oacc[nf][r] = 0.f;
    mma_pass(sl, 68, &Ss[0][0], 72, oacc);

    #pragma unroll
    for (int nf = 0; nf < 2; nf++) {
        int colb = wn * 16 + nf * 8 + t4 * 2;
        #pragma unroll
        for (int ch = 0; ch < 2; ch++) {
            int rl = wm * 16 + g + ch * 8;
            size_t off = (size_t)(rb + i0 + rl) * HH + h * 64 + colb;
            *(float2*)&o[off] = make_float2(oacc[ch == 0 ? nf : nf][ch * 2 + 0],
                                            oacc[nf][ch * 2 + 1]);
            // NOTE: identical to oacc[nf][ch*2+0/1]
            *(float2*)&o[off] = make_float2(oacc[nf][ch * 2 + 0], oacc[nf][ch * 2 + 1]);
        }
    }
}

// ---------------- batched [64,64] Gram over 512, cp.async pipelined -----------------
struct DJob { const float* A; const float* B; float* C; int strA, strB, strC; };
struct DParams { DJob jobs[16]; int n; };
__global__ __launch_bounds__(256) void gram_kernel(DParams P) {
    DJob job = P.jobs[blockIdx.x];
    int b = blockIdx.y;
    __shared__ float As[2][64][36];
    __shared__ float Bs[2][64][36];
    int tid = threadIdx.x;
    int lane = tid & 31, wid = tid >> 5;
    int wm = wid >> 2, wn = wid & 3;
    int g = lane >> 2, t4 = lane & 3;

    const float* Abase = job.A + (size_t)b * job.strA * HH;
    const float* Bbase = job.B + (size_t)b * job.strB * HH;

    int lrow = tid >> 2;
    int lc = tid & 3;

    float acc[2][2][4];
    #pragma unroll
    for (int mf = 0; mf < 2; mf++)
        #pragma unroll
        for (int nf = 0; nf < 2; nf++)
            #pragma unroll
            for (int r = 0; r < 4; r++) acc[mf][nf][r] = 0.f;

    {
        #pragma unroll
        for (int r = 0; r < 2; r++) {
            int c4 = lc + 4 * r;
            cpasync16(&As[0][lrow][c4 * 4], Abase + (size_t)lrow * HH + c4 * 4);
        }
        #pragma unroll
        for (int r = 0; r < 2; r++) {
            int c4 = lc + 4 * r;
            cpasync16(&Bs[0][lrow][c4 * 4], Bbase + (size_t)lrow * HH + c4 * 4);
        }
        asm volatile("cp.async.commit_group;\n");
    }

    for (int kc = 0; kc < 16; kc++) {
        if (kc + 1 < 16) {
            int st = (kc + 1) & 1;
            int k0 = (kc + 1) * 32;
            #pragma unroll
            for (int r = 0; r < 2; r++) {
                int c4 = lc + 4 * r;
                cpasync16(&As[st][lrow][c4 * 4], Abase + (size_t)lrow * HH + k0 + c4 * 4);
            }
            #pragma unroll
            for (int r = 0; r < 2; r++) {
                int c4 = lc + 4 * r;
                cpasync16(&Bs[st][lrow][c4 * 4], Bbase + (size_t)lrow * HH + k0 + c4 * 4);
            }
            asm volatile("cp.async.commit_group;\n");
            asm volatile("cp.async.wait_group 1;\n");
        } else {
            asm volatile("cp.async.wait_group 0;\n");
        }
        __syncthreads();
        int st = kc & 1;
        #pragma unroll
        for (int ks = 0; ks < 4; ks++) {
            uint32_t a[2][4], bb[2][2];
            #pragma unroll
            for (int mf = 0; mf < 2; mf++) {
                int r0 = wm * 32 + mf * 16;
                a[mf][0] = f2tf32(As[st][r0 + g][ks * 8 + t4]);
                a[mf][1] = f2tf32(As[st][r0 + 8 + g][ks * 8 + t4]);
                a[mf][2] = f2tf32(As[st][r0 + g][ks * 8 + t4 + 4]);
                a[mf][3] = f2tf32(As[st][r0 + 8 + g][ks * 8 + t4 + 4]);
            }
            #pragma unroll
            for (int nf = 0; nf < 2; nf++) {
                int c0 = wn * 16 + nf * 8;
                bb[nf][0] = f2tf32(Bs[st][c0 + g][ks * 8 + t4]);
                bb[nf][1] = f2tf32(Bs[st][c0 + g][ks * 8 + t4 + 4]);
            }
            #pragma unroll
            for (int mf = 0; mf < 2; mf++)
                #pragma unroll
                for (int nf = 0; nf < 2; nf++)
                    mma_tf32(acc[mf][nf], a[mf], bb[nf]);
        }
        __syncthreads();
    }
    float* out = job.C + (size_t)b * job.strC * 4096;
    #pragma unroll
    for (int mf = 0; mf < 2; mf++)
        #pragma unroll
        for (int nf = 0; nf < 2; nf++) {
            int colb = wn * 16 + nf * 8 + t4 * 2;
            #pragma unroll
            for (int half = 0; half < 2; half++) {
                int row = wm * 32 + mf * 16 + g + half * 8;
                *(float2*)&out[row * 64 + colb] = make_float2(acc[mf][nf][half * 2 + 0],
                                                              acc[mf][nf][half * 2 + 1]);
            }
        }
}

// ---------------- edge coefficient update ----------------
__global__ void edge_kernel(const int* __restrict__ adj,
                            const float* __restrict__ PG,
                            const float* __restrict__ PV,
                            const float* __restrict__ PX,
                            const float* __restrict__ G,
                            const float* __restrict__ VX,
                            float* __restrict__ p0,
                            float* __restrict__ pi,
                            float* __restrict__ pj,
                            int T) {
    int bij = blockIdx.x * blockDim.x + threadIdx.x; // 32768
    int b = bij >> 12;
    int ij = bij & 4095;
    int i = ij >> 6, j = ij & 63;
    int e = adj[bij];
    size_t tb = (size_t)b * 4096;

    float P0 = p0[bij];
    float s = P0 * P0 * PG[tb + e * 64 + e];
    float a0 = P0 * PX[tb + i * 64 + e];
    float a1 = P0 * PX[tb + j * 64 + e];

    float ci[3], cj[3];
    for (int t = 0; t < T; t++) { ci[t] = pi[t * NE + bij]; cj[t] = pj[t * NE + bij]; }

    for (int t = 0; t < T; t++) {
        const float* pv = PV + (size_t)t * NE + tb;
        s += 2.f * P0 * (ci[t] * pv[i * 64 + e] + cj[t] * pv[j * 64 + e]);
        const float* vx = VX + (size_t)t * NE + tb;
        a0 += ci[t] * vx[i * 64 + i] + cj[t] * vx[j * 64 + i];
        a1 += ci[t] * vx[i * 64 + j] + cj[t] * vx[j * 64 + j];
        for (int ss2 = 0; ss2 < T; ss2++) {
            const float* g = G + (size_t)(ss2 * 3 + t) * NE + tb;
            s += ci[ss2] * ci[t] * g[i * 64 + i]
               + cj[ss2] * cj[t] * g[j * 64 + j]
               + 2.f * ci[ss2] * cj[t] * g[i * 64 + j];
        }
    }

    float u0 = s * INV_SCALE, u1 = a0 * INV_SCALE, u2 = a1 * INV_SCALE;
    float mm = fmaxf(u0, fmaxf(u1, u2));
    float q0 = expf(u0 - mm), q1 = expf(u1 - mm), q2 = expf(u2 - mm);
    float inv = 1.f / (q0 + q1 + q2);
    float w0 = q0 * inv;

    p0[bij] = w0 * P0;
    for (int t = 0; t < T; t++) {
        pi[t * NE + bij] = w0 * ci[t];
        pj[t * NE + bij] = w0 * cj[t];
    }
    pi[T * NE + bij] = q1 * inv;
    pj[T * NE + bij] = q2 * inv;
}

// ---------------- head ----------------
__global__ __launch_bounds__(512) void head_kernel(const float* __restrict__ x,
                                                   const float* __restrict__ Wout,
                                                   const float* __restrict__ Wpred,
                                                   const float* __restrict__ bpred,
                                                   float* __restrict__ out) {
    int b = blockIdx.x;
    int t = threadIdx.x; // 512
    __shared__ float xb[HH];
    __shared__ float cvec[HH];
    __shared__ float r0[16], r1[16];
    xb[t] = x[(size_t)(b * NN) * HH + t];
    __syncthreads();
    float s = 0.f;
    #pragma unroll 8
    for (int h2 = 0; h2 < HH; h2++) s += xb[h2] * Wout[(size_t)h2 * HH + t];
    cvec[t] = tanhf(s);
    __syncthreads();
    float pr0 = cvec[t] * Wpred[t * 2 + 0];
    float pr1 = cvec[t] * Wpred[t * 2 + 1];
    pr0 = warpReduceSum(pr0);
    pr1 = warpReduceSum(pr1);
    int lane = t & 31, w = t >> 5;
    if (lane == 0) { r0[w] = pr0; r1[w] = pr1; }
    __syncthreads();
    if (t == 0) {
        float l0 = bpred[0], l1 = bpred[1];
        #pragma unroll
        for (int q2 = 0; q2 < 16; q2++) { l0 += r0[q2]; l1 += r1[q2]; }
        float m = fmaxf(l0, l1);
        float e0 = expf(l0 - m), e1 = expf(l1 - m);
        float inv = 1.f / (e0 + e1);
        out[b * 2 + 0] = e0 * inv;
        out[b * 2 + 1] = e1 * inv;
    }
}

// ---------------- orchestration ----------------
extern "C" void kernel_launch(void* const* d_in, const int* in_sizes, int n_in,
                              void* d_out, int out_size) {
    const int* input_batch = (const int*)d_in[0];
    const int* adj = (const int*)d_in[1];
    const float* atom_emb = (const float*)d_in[2];
    const float* bond_emb = (const float*)d_in[3];
    const float* Wq = (const float*)d_in[4];
    const float* Wk = (const float*)d_in[5];
    const float* Wv = (const float*)d_in[6];
    const float* Wew = (const float*)d_in[7];
    const float* Wstack = (const float*)d_in[8];
    const float* Wf1 = (const float*)d_in[9];
    const float* Wf2 = (const float*)d_in[10];
    const float* Wout = (const float*)d_in[11];
    const float* Wpred = (const float*)d_in[12];
    const float* bpred = (const float*)d_in[13];
    float* out = (float*)d_out;

    static cudaStream_t sA = nullptr;
    static cudaEvent_t evFork = nullptr, evMid = nullptr, evA = nullptr;
    static int initDone = 0;
    if (!initDone) {
        cudaStreamCreateWithFlags(&sA, cudaStreamNonBlocking);
        cudaEventCreateWithFlags(&evFork, cudaEventDisableTiming);
        cudaEventCreateWithFlags(&evMid, cudaEventDisableTiming);
        cudaEventCreateWithFlags(&evA, cudaEventDisableTiming);
        initDone = 1;
    }

    float *x, *xn, *q, *k, *v, *o, *resid, *h1, *ff, *part, *Va, *Vb, *PsiA, *PsiB;
    float *p0, *pi, *pj, *PV, *PX, *PsiGram, *G, *VX;
    cudaGetSymbolAddress((void**)&x, g_x);
    cudaGetSymbolAddress((void**)&xn, g_xn);
    cudaGetSymbolAddress((void**)&q, g_q);
    cudaGetSymbolAddress((void**)&k, g_k);
    cudaGetSymbolAddress((void**)&v, g_v);
    cudaGetSymbolAddress((void**)&o, g_o);
    cudaGetSymbolAddress((void**)&resid, g_resid);
    cudaGetSymbolAddress((void**)&h1, g_h1);
    cudaGetSymbolAddress((void**)&ff, g_ff);
    cudaGetSymbolAddress((void**)&part, g_part);
    cudaGetSymbolAddress((void**)&Va, g_Va);
    cudaGetSymbolAddress((void**)&Vb, g_Vb);
    cudaGetSymbolAddress((void**)&PsiA, g_PsiA);
    cudaGetSymbolAddress((void**)&PsiB, g_PsiB);
    cudaGetSymbolAddress((void**)&p0, g_p0);
    cudaGetSymbolAddress((void**)&pi, g_pi);
    cudaGetSymbolAddress((void**)&pj, g_pj);
    cudaGetSymbolAddress((void**)&PV, g_PV);
    cudaGetSymbolAddress((void**)&PX, g_PX);
    cudaGetSymbolAddress((void**)&PsiGram, g_PsiGram);
    cudaGetSymbolAddress((void**)&G, g_G);
    cudaGetSymbolAddress((void**)&VX, g_VX);

    float* P0b = part;
    float* P1b = part + (size_t)ROWS * HH;
    float* P2b = part + (size_t)2 * ROWS * HH;
    float* P3b = part + (size_t)3 * ROWS * HH;

    init_ln_kernel<<<ROWS, 128>>>(input_batch, atom_emb, bond_emb, x, xn, PsiA, p0);

    float* VbufA[3] = {Va, Va + ROWS * HH, Va + 2 * ROWS * HH};
    float* VbufB[3] = {Vb, Vb + ROWS * HH, Vb + 2 * ROWS * HH};
    float* prevDst[3] = {nullptr, nullptr, nullptr};
    bool pendingA = false;

    for (int l = 0; l < NLAYERS; l++) {
        const float* Wq_l = Wq + (size_t)l * HH * HH;
        const float* Wk_l = Wk + (size_t)l * HH * HH;
        const float* Wv_l = Wv + (size_t)l * HH * HH;
        const float* Wew_l = Wew + (size_t)l * HH * HH;
        const float* Wst_l = Wstack + (size_t)l * HH * HH;
        const float* Wf1_l = Wf1 + (size_t)l * HH * FFD;
        const float* Wf2_l = Wf2 + (size_t)l * FFD * HH;

        int T = l;
        float** dst = (l & 1) ? VbufA : VbufB;
        const float* src[3];
        for (int t = 0; t < T - 1; t++) src[t] = prevDst[t];
        if (T > 0) src[T - 1] = x;
        float* psiSrc = (l & 1) ? PsiB : PsiA;
        float* psiDst = (l & 1) ? PsiA : PsiB;

        // 1) fused GEMMs: q,k,v + V'_t + Psi'
        {
            GParams Pm;
            int nb = 0, blk = 0;
            auto add = [&](const float* A, const float* B2, float* C2, int M, int N2, int K2) {
                Pm.jobs[nb] = {A, B2, nullptr, C2, M, N2, K2, 0, blk, 0, K2};
                blk += (M / 64) * (N2 / 64);
                nb++;
            };
            add(xn, Wq_l, q, ROWS, HH, HH);
            add(xn, Wk_l, k, ROWS, HH, HH);
            add(xn, Wv_l, v, ROWS, HH, HH);
            for (int t = 0; t < T; t++) add(src[t], Wew_l, dst[t], ROWS, HH, HH);
            add(psiSrc, Wew_l, psiDst, 64, HH, HH);
            Pm.nJobs = nb;
            gemm_tc_kernel<<<blk, 256>>>(Pm);
        }

        // early fork: G[s,t], PV_t, PsiGram — needs only dst/psiDst
        if (l < NLAYERS - 1) {
            cudaEventRecord(evFork, 0);
            cudaStreamWaitEvent(sA, evFork, 0);
            DParams DP;
            int nj = 0;
            for (int s = 0; s < T; s++)
                for (int t = 0; t < T; t++)
                    DP.jobs[nj++] = {dst[s], dst[t], G + (size_t)(s * 3 + t) * NE, 64, 64, 1};
            for (int t = 0; t < T; t++)
                DP.jobs[nj++] = {dst[t], psiDst, PV + (size_t)t * NE, 64, 0, 1};
            DP.jobs[nj++] = {psiDst, psiDst, PsiGram, 0, 0, 1};
            DP.n = nj;
            dim3 gg(nj, BB);
            gram_kernel<<<gg, 256, 0, sA>>>(DP);
        }

        // join previous layer's edge_kernel before attention
        if (pendingA) {
            cudaStreamWaitEvent(0, evA, 0);
            pendingA = false;
        }

        // 2) fused attention: 2 CTAs per (b,h)
        attn_fused_kernel<<<BB * NHEADS * 2, 256>>>(q, k, v,
                                                T > 0 ? dst[0] : nullptr,
                                                T > 1 ? dst[1] : nullptr,
                                                T > 2 ? dst[2] : nullptr,
                                                psiDst, adj, p0, pi, pj, T, o);

        // 3) stack GEMM, split-K x4
        {
            GParams Pm;
            for (int sK = 0; sK < 4; sK++)
                Pm.jobs[sK] = {o, Wst_l, nullptr, part + (size_t)sK * ROWS * HH,
                               ROWS, HH, HH, 0, sK * 64, sK * 128, 128};
            Pm.nJobs = 4;
            gemm_tc_kernel<<<256, 256>>>(Pm);
        }
        // 4) resid = sum(P)+xn ; h1 = LN(resid)
        ln_combine_kernel<<<ROWS, 128>>>(P0b, P1b, P2b, P3b, xn, resid, h1);

        // 5) FF1 (relu)
        {
            GParams Pm;
            Pm.jobs[0] = {h1, Wf1_l, nullptr, ff, ROWS, FFD, HH, 2, 0, 0, HH};
            Pm.nJobs = 1;
            gemm_tc_kernel<<<(ROWS / 64) * (FFD / 64), 256>>>(Pm);
        }
        // 6) FF2 split-K x4
        {
            GParams Pm;
            for (int sK = 0; sK < 4; sK++)
                Pm.jobs[sK] = {ff, Wf2_l, nullptr, part + (size_t)sK * ROWS * HH,
                               ROWS, HH, FFD, 0, sK * 64, sK * 512, 512};
            Pm.nJobs = 4;
            gemm_tc_kernel<<<256, 256>>>(Pm);
        }
        // 7) x = sum(P) + resid ; xn = LN(x)
        ln_combine_kernel<<<ROWS, 128>>>(P0b, P1b, P2b, P3b, resid, x, xn);

        // late fork: VX_t + PX (need x) as gram jobs, then edge update
        if (l < NLAYERS - 1) {
            cudaEventRecord(evMid, 0);
            cudaStreamWaitEvent(sA, evMid, 0);
            DParams DP;
            int nj = 0;
            for (int t = 0; t < T; t++)
                DP.jobs[nj++] = {dst[t], x, VX + (size_t)t * NE, 64, 64, 1};
            DP.jobs[nj++] = {x, psiDst, PX, 64, 0, 1};
            DP.n = nj;
            dim3 gg(nj, BB);
            gram_kernel<<<gg, 256, 0, sA>>>(DP);
            edge_kernel<<<NE / 256, 256, 0, sA>>>(adj, PsiGram, PV, PX, G, VX, p0, pi, pj, T);
            cudaEventRecord(evA, sA);
            pendingA = true;
        }

        prevDst[0] = dst[0]; prevDst[1] = dst[1]; prevDst[2] = dst[2];
    }

    head_kernel<<<BB, 512>>>(x, Wout, Wpred, bpred, out);
}